// round 6
// baseline (speedup 1.0000x reference)
#include <cuda_runtime.h>
#include <cuda_bf16.h>
#include <cstdint>

// Problem constants
#define NBLK   4
#define DIM    256
#define DSTATE 16
#define DCONV  4
#define DIN    512      // EXPAND * DIM
#define DTRANK 16
#define BB     16
#define LL     512
#define TOK    (BB * LL)          // 8192 tokens
#define DBC_N  (DTRANK + 2 * DSTATE)  // 48

// ---------------------------------------------------------------------------
// Scratch (static device globals; no runtime allocation allowed)
// ---------------------------------------------------------------------------
__device__ float g_h   [TOK * DIM];   // layernorm output
__device__ float g_xin [TOK * DIN];   // conv input (first half of in_proj out)
__device__ float g_silz[TOK * DIN];   // silu(z) (second half of in_proj out)
__device__ float g_xc  [TOK * DIN];   // conv+silu output (= u for the scan)
__device__ float g_dbc [TOK * DBC_N]; // x_proj output (dt_in | B | C)
__device__ float g_dt  [TOK * DIN];   // softplus(dt)
__device__ float g_g   [TOK * DIN];   // (y + u*D) * silu(z), input to out_proj

// ---------------------------------------------------------------------------
// Helpers
// ---------------------------------------------------------------------------
__device__ __forceinline__ float siluf(float v) {
    return v / (1.0f + __expf(-v));
}
__device__ __forceinline__ float softplusf(float v) {
    return (v > 20.0f) ? v : log1pf(__expf(v));
}

// ---------------------------------------------------------------------------
// LayerNorm: one warp per token (DIM=256 -> 8 floats/lane as 2x float4)
// ---------------------------------------------------------------------------
__global__ void ln_kernel(const float* __restrict__ x,
                          const float* __restrict__ w,
                          const float* __restrict__ b,
                          float* __restrict__ out)
{
    int warpsPerBlock = blockDim.x >> 5;
    int t    = blockIdx.x * warpsPerBlock + (threadIdx.x >> 5);
    int lane = threadIdx.x & 31;
    if (t >= TOK) return;

    const float4* xr = reinterpret_cast<const float4*>(x + (size_t)t * DIM);
    float4 v0 = xr[lane];
    float4 v1 = xr[lane + 32];

    float s  = v0.x + v0.y + v0.z + v0.w + v1.x + v1.y + v1.z + v1.w;
    float ss = v0.x*v0.x + v0.y*v0.y + v0.z*v0.z + v0.w*v0.w
             + v1.x*v1.x + v1.y*v1.y + v1.z*v1.z + v1.w*v1.w;
    #pragma unroll
    for (int o = 16; o > 0; o >>= 1) {
        s  += __shfl_xor_sync(0xffffffffu, s,  o);
        ss += __shfl_xor_sync(0xffffffffu, ss, o);
    }
    float mu  = s * (1.0f / DIM);
    float var = ss * (1.0f / DIM) - mu * mu;
    float inv = rsqrtf(var + 1e-5f);

    const float4* wr = reinterpret_cast<const float4*>(w);
    const float4* br = reinterpret_cast<const float4*>(b);
    float4 w0 = wr[lane], w1 = wr[lane + 32];
    float4 b0 = br[lane], b1 = br[lane + 32];

    float4 o0, o1;
    o0.x = (v0.x - mu) * inv * w0.x + b0.x;
    o0.y = (v0.y - mu) * inv * w0.y + b0.y;
    o0.z = (v0.z - mu) * inv * w0.z + b0.z;
    o0.w = (v0.w - mu) * inv * w0.w + b0.w;
    o1.x = (v1.x - mu) * inv * w1.x + b1.x;
    o1.y = (v1.y - mu) * inv * w1.y + b1.y;
    o1.z = (v1.z - mu) * inv * w1.z + b1.z;
    o1.w = (v1.w - mu) * inv * w1.w + b1.w;

    float4* orow = reinterpret_cast<float4*>(out + (size_t)t * DIM);
    orow[lane]      = o0;
    orow[lane + 32] = o1;
}

// ---------------------------------------------------------------------------
// Generic register-blocked SIMT GEMM:  C[M,N] = A[M,K] @ W[N,K]^T  (+ epilogue)
// MODE 0: in_proj  -> +bias; col<DIN to C0 (xin), col>=DIN silu -> C1 (silz)
// MODE 1: x_proj   -> plain store to C0
// MODE 2: out_proj -> C0[.] = C1[.] + v   (residual add; C0==C1 is fine:
//                     each element read+written by exactly one thread)
// Requires M%BM==0, N%BN==0, K%BK==0 (true for all call sites here).
// ---------------------------------------------------------------------------
template<int BM, int BN, int BK, int TM, int TN, int MODE>
__global__ void __launch_bounds__((BM/TM)*(BN/TN))
gemm_kernel(const float* __restrict__ A,
            const float* __restrict__ W,
            const float* __restrict__ bias,
            float* __restrict__ C0,
            float* __restrict__ C1,
            int M, int N, int K)
{
    constexpr int THREADS = (BM / TM) * (BN / TN);
    constexpr int BKV = BK / 4;

    __shared__ float As[BK][BM + 4];
    __shared__ float Ws[BK][BN + 4];

    const int tid = threadIdx.x;
    const int tx  = tid % (BN / TN);
    const int ty  = tid / (BN / TN);
    const int m0  = blockIdx.y * BM;
    const int n0  = blockIdx.x * BN;

    float acc[TM][TN];
    #pragma unroll
    for (int i = 0; i < TM; i++)
        #pragma unroll
        for (int j = 0; j < TN; j++) acc[i][j] = 0.0f;

    for (int k0 = 0; k0 < K; k0 += BK) {
        // Load A tile (BM x BK) as float4 along K, store transposed
        constexpr int AV = BM * BK / 4;
        #pragma unroll
        for (int i = tid; i < AV; i += THREADS) {
            int r  = i / BKV;
            int c4 = i % BKV;
            float4 v = *reinterpret_cast<const float4*>(
                A + (size_t)(m0 + r) * K + k0 + c4 * 4);
            As[c4 * 4 + 0][r] = v.x;
            As[c4 * 4 + 1][r] = v.y;
            As[c4 * 4 + 2][r] = v.z;
            As[c4 * 4 + 3][r] = v.w;
        }
        // Load W tile (BN x BK)
        constexpr int WV = BN * BK / 4;
        #pragma unroll
        for (int i = tid; i < WV; i += THREADS) {
            int r  = i / BKV;
            int c4 = i % BKV;
            float4 v = *reinterpret_cast<const float4*>(
                W + (size_t)(n0 + r) * K + k0 + c4 * 4);
            Ws[c4 * 4 + 0][r] = v.x;
            Ws[c4 * 4 + 1][r] = v.y;
            Ws[c4 * 4 + 2][r] = v.z;
            Ws[c4 * 4 + 3][r] = v.w;
        }
        __syncthreads();

        #pragma unroll
        for (int kk = 0; kk < BK; kk++) {
            float a[TM], bb[TN];
            #pragma unroll
            for (int i = 0; i < TM; i++) a[i]  = As[kk][ty * TM + i];
            #pragma unroll
            for (int j = 0; j < TN; j++) bb[j] = Ws[kk][tx * TN + j];
            #pragma unroll
            for (int i = 0; i < TM; i++)
                #pragma unroll
                for (int j = 0; j < TN; j++)
                    acc[i][j] = fmaf(a[i], bb[j], acc[i][j]);
        }
        __syncthreads();
    }

    #pragma unroll
    for (int i = 0; i < TM; i++) {
        int row = m0 + ty * TM + i;
        #pragma unroll
        for (int j = 0; j < TN; j++) {
            int col = n0 + tx * TN + j;
            float v = acc[i][j];
            if (MODE == 0) {
                v += bias[col];
                if (col < DIN) C0[(size_t)row * DIN + col] = v;
                else           C1[(size_t)row * DIN + (col - DIN)] = siluf(v);
            } else if (MODE == 1) {
                C0[(size_t)row * N + col] = v;
            } else {
                C0[(size_t)row * N + col] = C1[(size_t)row * N + col] + v;
            }
        }
    }
}

// ---------------------------------------------------------------------------
// Causal depthwise conv (DCONV=4) + bias + SiLU.  One thread per (token, ch).
// xc[b,l,c] = silu( sum_{k=0..3} xin[b, l-3+k, c] * cw[c,k] + cb[c] )
// ---------------------------------------------------------------------------
__global__ void conv_kernel(const float* __restrict__ xin,
                            const float* __restrict__ cw,
                            const float* __restrict__ cb,
                            float* __restrict__ xc)
{
    int idx = blockIdx.x * blockDim.x + threadIdx.x;
    if (idx >= TOK * DIN) return;
    int c = idx % DIN;
    int t = idx / DIN;
    int l = t % LL;

    float w0 = cw[c * DCONV + 0];
    float w1 = cw[c * DCONV + 1];
    float w2 = cw[c * DCONV + 2];
    float w3 = cw[c * DCONV + 3];

    float acc = cb[c];
    if (l >= 3) acc = fmaf(xin[idx - 3 * DIN], w0, acc);
    if (l >= 2) acc = fmaf(xin[idx - 2 * DIN], w1, acc);
    if (l >= 1) acc = fmaf(xin[idx - 1 * DIN], w2, acc);
    acc = fmaf(xin[idx], w3, acc);
    xc[idx] = siluf(acc);
}

// ---------------------------------------------------------------------------
// dt = softplus( dbc[:, :DTRANK] @ dtw^T + dtb ).  One thread per (token, d).
// ---------------------------------------------------------------------------
__global__ void dt_kernel(const float* __restrict__ dbc,
                          const float* __restrict__ dtw,
                          const float* __restrict__ dtb,
                          float* __restrict__ dt)
{
    int idx = blockIdx.x * blockDim.x + threadIdx.x;
    if (idx >= TOK * DIN) return;
    int d = idx % DIN;
    int t = idx / DIN;

    const float* r  = dbc + (size_t)t * DBC_N;
    const float* wv = dtw + (size_t)d * DTRANK;
    float acc = dtb[d];
    #pragma unroll
    for (int i = 0; i < DTRANK; i++) acc = fmaf(r[i], wv[i], acc);
    dt[idx] = softplusf(acc);
}

// ---------------------------------------------------------------------------
// Selective scan + gating.
// 16 lanes per (b,d) channel, lane n holds state n. y via 4x shfl.xor reduce.
// Output: g[t,d] = (y + u*D[d]) * silu(z)[t,d]
// ---------------------------------------------------------------------------
__global__ void __launch_bounds__(256)
scan_kernel(const float* __restrict__ dt,
            const float* __restrict__ dbc,
            const float* __restrict__ u,      // xc
            const float* __restrict__ A_log,  // (DIN, DSTATE) for this block
            const float* __restrict__ Dv,     // (DIN)
            const float* __restrict__ silz,
            float* __restrict__ g)
{
    int tid = threadIdx.x;
    int n   = tid & 15;
    int ch  = blockIdx.x * 16 + (tid >> 4);   // ch = b*DIN + d
    int b   = ch >> 9;                        // / DIN
    int d   = ch & (DIN - 1);

    float An = -__expf(A_log[d * DSTATE + n]);
    float Dd = Dv[d];
    float h  = 0.0f;
    int tbase = b * LL;

    #pragma unroll 4
    for (int l = 0; l < LL; l++) {
        int t = tbase + l;
        float dtv = dt[(size_t)t * DIN + d];
        float uv  = u [(size_t)t * DIN + d];
        float Bn  = dbc[(size_t)t * DBC_N + DTRANK + n];
        float Cn  = dbc[(size_t)t * DBC_N + DTRANK + DSTATE + n];

        float dA = __expf(dtv * An);
        h = fmaf(dA, h, dtv * Bn * uv);

        float p = h * Cn;
        p += __shfl_xor_sync(0xffffffffu, p, 8);
        p += __shfl_xor_sync(0xffffffffu, p, 4);
        p += __shfl_xor_sync(0xffffffffu, p, 2);
        p += __shfl_xor_sync(0xffffffffu, p, 1);

        if (n == 0) {
            float y = p + uv * Dd;
            g[(size_t)t * DIN + d] = y * silz[(size_t)t * DIN + d];
        }
    }
}

// ---------------------------------------------------------------------------
// Launcher
// ---------------------------------------------------------------------------
extern "C" void kernel_launch(void* const* d_in, const int* in_sizes, int n_in,
                              void* d_out, int out_size)
{
    const float* x    = (const float*)d_in[0];
    const float* ln_w = (const float*)d_in[1];
    const float* ln_b = (const float*)d_in[2];
    const float* in_w = (const float*)d_in[3];
    const float* in_b = (const float*)d_in[4];
    const float* cw   = (const float*)d_in[5];
    const float* cb   = (const float*)d_in[6];
    const float* xp_w = (const float*)d_in[7];
    const float* dt_w = (const float*)d_in[8];
    const float* dt_b = (const float*)d_in[9];
    const float* A_lg = (const float*)d_in[10];
    const float* Dv   = (const float*)d_in[11];
    const float* ow   = (const float*)d_in[12];

    float *p_h, *p_xin, *p_silz, *p_xc, *p_dbc, *p_dt, *p_g;
    cudaGetSymbolAddress((void**)&p_h,    g_h);
    cudaGetSymbolAddress((void**)&p_xin,  g_xin);
    cudaGetSymbolAddress((void**)&p_silz, g_silz);
    cudaGetSymbolAddress((void**)&p_xc,   g_xc);
    cudaGetSymbolAddress((void**)&p_dbc,  g_dbc);
    cudaGetSymbolAddress((void**)&p_dt,   g_dt);
    cudaGetSymbolAddress((void**)&p_g,    g_g);

    float* xres = (float*)d_out;  // running residual buffer (= final output)
    cudaMemcpyAsync(xres, x, (size_t)TOK * DIM * sizeof(float),
                    cudaMemcpyDeviceToDevice, 0);

    for (int nb = 0; nb < NBLK; nb++) {
        const float* lnw = ln_w + nb * DIM;
        const float* lnb = ln_b + nb * DIM;
        const float* inw = in_w + (size_t)nb * 2 * DIN * DIM;
        const float* inb = in_b + nb * 2 * DIN;
        const float* cwn = cw   + (size_t)nb * DIN * DCONV;
        const float* cbn = cb   + nb * DIN;
        const float* xpw = xp_w + (size_t)nb * DBC_N * DIN;
        const float* dtw = dt_w + (size_t)nb * DIN * DTRANK;
        const float* dtb = dt_b + nb * DIN;
        const float* alg = A_lg + (size_t)nb * DIN * DSTATE;
        const float* dvn = Dv   + nb * DIN;
        const float* own = ow   + (size_t)nb * DIM * DIN;

        // 1. LayerNorm (8 warps/block = 8 tokens/block)
        ln_kernel<<<TOK / 8, 256>>>(xres, lnw, lnb, p_h);

        // 2. in_proj GEMM: (8192,256) @ (256,1024) -> xin | silu(z)
        gemm_kernel<128, 128, 16, 8, 8, 0>
            <<<dim3(2 * DIN / 128, TOK / 128), 256>>>(
                p_h, inw, inb, p_xin, p_silz, TOK, 2 * DIN, DIM);

        // 3. Causal depthwise conv + SiLU
        conv_kernel<<<(TOK * DIN) / 256, 256>>>(p_xin, cwn, cbn, p_xc);

        // 4. x_proj GEMM: (8192,512) @ (512,48) -> dbc
        gemm_kernel<64, 48, 16, 4, 3, 1>
            <<<dim3(1, TOK / 64), 256>>>(
                p_xc, xpw, nullptr, p_dbc, nullptr, TOK, DBC_N, DIN);

        // 5. dt projection + softplus
        dt_kernel<<<(TOK * DIN) / 256, 256>>>(p_dbc, dtw, dtb, p_dt);

        // 6. Selective scan + D skip + gating
        scan_kernel<<<(BB * DIN) / 16, 256>>>(
            p_dt, p_dbc, p_xc, alg, dvn, p_silz, p_g);

        // 7. out_proj GEMM + residual: xres += g @ ow^T
        gemm_kernel<128, 64, 16, 8, 4, 2>
            <<<dim3(DIM / 64, TOK / 128), 256>>>(
                p_g, own, nullptr, xres, xres, TOK, DIM, DIN);
    }
}

// round 10
// speedup vs baseline: 1.2031x; 1.2031x over previous
#include <cuda_runtime.h>
#include <cuda_bf16.h>
#include <cstdint>

// Problem constants
#define NBLK   4
#define DIM    256
#define DSTATE 16
#define DCONV  4
#define DIN    512      // EXPAND * DIM
#define DTRANK 16
#define BB     16
#define LL     512
#define TOK    (BB * LL)              // 8192 tokens
#define DBC_N  (DTRANK + 2 * DSTATE)  // 48

// ---------------------------------------------------------------------------
// Scratch (static device globals; no runtime allocation allowed)
// ---------------------------------------------------------------------------
__device__ float g_h   [TOK * DIM];   // layernorm output
__device__ float g_xin [TOK * DIN];   // conv input (first half of in_proj out)
__device__ float g_silz[TOK * DIN];   // silu(z) (second half of in_proj out)
__device__ float g_xc  [TOK * DIN];   // conv+silu output (= u for the scan)
__device__ float g_dbc [TOK * DBC_N]; // x_proj output (dt_in | B | C)
__device__ float g_dt  [TOK * DIN];   // softplus(dt)
__device__ float g_g   [TOK * DIN];   // (y + u*D) * silu(z), input to out_proj

// ---------------------------------------------------------------------------
// Helpers
// ---------------------------------------------------------------------------
__device__ __forceinline__ float siluf(float v) {
    return v / (1.0f + __expf(-v));
}
__device__ __forceinline__ float softplusf(float v) {
    return (v > 20.0f) ? v : log1pf(__expf(v));
}
__device__ __forceinline__ uint32_t smem_u32(const void* p) {
    uint32_t a;
    asm("{ .reg .u64 t; cvta.to.shared.u64 t, %1; cvt.u32.u64 %0, t; }"
        : "=r"(a) : "l"(p));
    return a;
}

// bf16 hi/lo split of a float4 (hi + lo reproduces fp32 to ~2^-24)
__device__ __forceinline__ uint32_t pack_bf16(__nv_bfloat16 a, __nv_bfloat16 b) {
    return (uint32_t)__bfloat16_as_ushort(a) |
           ((uint32_t)__bfloat16_as_ushort(b) << 16);
}
__device__ __forceinline__ void split4(float4 v, uint2& hi, uint2& lo) {
    __nv_bfloat16 h0 = __float2bfloat16(v.x);
    __nv_bfloat16 h1 = __float2bfloat16(v.y);
    __nv_bfloat16 h2 = __float2bfloat16(v.z);
    __nv_bfloat16 h3 = __float2bfloat16(v.w);
    __nv_bfloat16 l0 = __float2bfloat16(v.x - __bfloat162float(h0));
    __nv_bfloat16 l1 = __float2bfloat16(v.y - __bfloat162float(h1));
    __nv_bfloat16 l2 = __float2bfloat16(v.z - __bfloat162float(h2));
    __nv_bfloat16 l3 = __float2bfloat16(v.w - __bfloat162float(h3));
    hi = make_uint2(pack_bf16(h0, h1), pack_bf16(h2, h3));
    lo = make_uint2(pack_bf16(l0, l1), pack_bf16(l2, l3));
}

// mma.sync m16n8k16 bf16 (baseline PTX, sm_80+; legal on compute_103)
__device__ __forceinline__ void mma16816(float* c, const uint32_t* a,
                                         const uint32_t* b) {
    asm volatile(
        "mma.sync.aligned.m16n8k16.row.col.f32.bf16.bf16.f32 "
        "{%0,%1,%2,%3}, {%4,%5,%6,%7}, {%8,%9}, {%0,%1,%2,%3};"
        : "+f"(c[0]), "+f"(c[1]), "+f"(c[2]), "+f"(c[3])
        : "r"(a[0]), "r"(a[1]), "r"(a[2]), "r"(a[3]), "r"(b[0]), "r"(b[1]));
}
__device__ __forceinline__ void ldm_x4(uint32_t* r, uint32_t addr) {
    asm volatile("ldmatrix.sync.aligned.m8n8.x4.shared.b16 {%0,%1,%2,%3}, [%4];"
                 : "=r"(r[0]), "=r"(r[1]), "=r"(r[2]), "=r"(r[3]) : "r"(addr));
}

// ===========================================================================
// HMMA GEMM: C[M,N] = A[M,K] @ W[N,K]^T, fp32 via bf16 hi/lo 3-term split.
// CTA: 128(M) x 128(N), 256 threads (8 warps, grid 2m x 4n, warp tile 64x32).
// K chunked by 32. MODE 0: in_proj epilogue. MODE 2: out_proj (+residual).
// ===========================================================================
template<int MODE, int KTOT>
__global__ void __launch_bounds__(256)
gemm_mma(const float* __restrict__ A, const float* __restrict__ W,
         const float* __restrict__ bias, float* __restrict__ C0,
         float* __restrict__ C1, int N)
{
    constexpr int KC  = 32;
    constexpr int LDT = 40;   // bf16 elems per row (pad 8 -> conflict-free ldmatrix)

    __shared__ __align__(16) __nv_bfloat16 sAhi[128 * LDT];
    __shared__ __align__(16) __nv_bfloat16 sAlo[128 * LDT];
    __shared__ __align__(16) __nv_bfloat16 sWhi[128 * LDT];
    __shared__ __align__(16) __nv_bfloat16 sWlo[128 * LDT];

    const int tid  = threadIdx.x;
    const int lane = tid & 31;
    const int wid  = tid >> 5;
    const int wm   = wid & 1;        // 0..1 -> m offset 0/64
    const int wn   = wid >> 1;       // 0..3 -> n offset 0/32/64/96
    const int m0   = blockIdx.y * 128;
    const int n0   = blockIdx.x * 128;

    const uint32_t bAhi = smem_u32(sAhi);
    const uint32_t bAlo = smem_u32(sAlo);
    const uint32_t bWhi = smem_u32(sWhi);
    const uint32_t bWlo = smem_u32(sWlo);

    float acc[4][4][4];
    #pragma unroll
    for (int i = 0; i < 4; i++)
        #pragma unroll
        for (int j = 0; j < 4; j++)
            #pragma unroll
            for (int k = 0; k < 4; k++) acc[i][j][k] = 0.0f;

    // ldmatrix address components (bf16 element offsets, x2 for bytes)
    const int arow = wm * 64 + (lane & 15);
    const int acol = (lane >> 4) * 8;
    const int bgrp = lane >> 3;
    const int brow = wn * 32 + (lane & 7) + ((bgrp >> 1) << 3);
    const int bcol = (bgrp & 1) * 8;

    #pragma unroll 1
    for (int k0 = 0; k0 < KTOT; k0 += KC) {
        // -------- load + convert fp32 -> bf16 hi/lo tiles --------
        #pragma unroll
        for (int i = tid; i < 1024; i += 256) {   // 128 rows x 8 float4
            int r  = i >> 3;
            int c4 = i & 7;
            uint2 hi, lo;
            float4 va = *reinterpret_cast<const float4*>(
                A + (size_t)(m0 + r) * KTOT + k0 + c4 * 4);
            split4(va, hi, lo);
            *reinterpret_cast<uint2*>(&sAhi[r * LDT + c4 * 4]) = hi;
            *reinterpret_cast<uint2*>(&sAlo[r * LDT + c4 * 4]) = lo;
            float4 vw = *reinterpret_cast<const float4*>(
                W + (size_t)(n0 + r) * KTOT + k0 + c4 * 4);
            split4(vw, hi, lo);
            *reinterpret_cast<uint2*>(&sWhi[r * LDT + c4 * 4]) = hi;
            *reinterpret_cast<uint2*>(&sWlo[r * LDT + c4 * 4]) = lo;
        }
        __syncthreads();

        // -------- 2 x k16 MMA steps --------
        #pragma unroll
        for (int kk = 0; kk < 2; kk++) {
            uint32_t ahi[4][4], alo[4][4];
            #pragma unroll
            for (int mi = 0; mi < 4; mi++) {
                uint32_t off = (uint32_t)(((arow + mi * 16) * LDT) + kk * 16 + acol) * 2;
                ldm_x4(ahi[mi], bAhi + off);
                ldm_x4(alo[mi], bAlo + off);
            }
            uint32_t bhi[8], blo[8];   // 4 n8 frags x 2 regs
            #pragma unroll
            for (int ni = 0; ni < 2; ni++) {
                uint32_t off = (uint32_t)(((brow + ni * 16) * LDT) + kk * 16 + bcol) * 2;
                ldm_x4(bhi + ni * 4, bWhi + off);
                ldm_x4(blo + ni * 4, bWlo + off);
            }
            #pragma unroll
            for (int mi = 0; mi < 4; mi++)
                #pragma unroll
                for (int nj = 0; nj < 4; nj++) {
                    mma16816(acc[mi][nj], ahi[mi], bhi + nj * 2);
                    mma16816(acc[mi][nj], ahi[mi], blo + nj * 2);
                    mma16816(acc[mi][nj], alo[mi], bhi + nj * 2);
                }
        }
        __syncthreads();
    }

    // -------- epilogue --------
    const int r0 = lane >> 2;
    const int c0 = (lane & 3) * 2;
    #pragma unroll
    for (int mi = 0; mi < 4; mi++) {
        #pragma unroll
        for (int nj = 0; nj < 4; nj++) {
            int row = m0 + wm * 64 + mi * 16 + r0;
            int col = n0 + wn * 32 + nj * 8 + c0;
            #pragma unroll
            for (int half = 0; half < 2; half++) {
                int rr = row + half * 8;
                float v0 = acc[mi][nj][half * 2 + 0];
                float v1 = acc[mi][nj][half * 2 + 1];
                if (MODE == 0) {
                    v0 += bias[col];
                    v1 += bias[col + 1];
                    if (n0 < DIN) {   // whole CTA tile on one side (DIN%128==0)
                        float2* p = reinterpret_cast<float2*>(
                            C0 + (size_t)rr * DIN + col);
                        *p = make_float2(v0, v1);
                    } else {
                        float2* p = reinterpret_cast<float2*>(
                            C1 + (size_t)rr * DIN + (col - DIN));
                        *p = make_float2(siluf(v0), siluf(v1));
                    }
                } else {
                    float2 r0v = *reinterpret_cast<const float2*>(
                        C1 + (size_t)rr * N + col);
                    float2* p = reinterpret_cast<float2*>(
                        C0 + (size_t)rr * N + col);
                    *p = make_float2(r0v.x + v0, r0v.y + v1);
                }
            }
        }
    }
}

// ---------------------------------------------------------------------------
// LayerNorm: one warp per token (DIM=256 -> 8 floats/lane as 2x float4)
// ---------------------------------------------------------------------------
__global__ void ln_kernel(const float* __restrict__ x,
                          const float* __restrict__ w,
                          const float* __restrict__ b,
                          float* __restrict__ out)
{
    int warpsPerBlock = blockDim.x >> 5;
    int t    = blockIdx.x * warpsPerBlock + (threadIdx.x >> 5);
    int lane = threadIdx.x & 31;
    if (t >= TOK) return;

    const float4* xr = reinterpret_cast<const float4*>(x + (size_t)t * DIM);
    float4 v0 = xr[lane];
    float4 v1 = xr[lane + 32];

    float s  = v0.x + v0.y + v0.z + v0.w + v1.x + v1.y + v1.z + v1.w;
    float ss = v0.x*v0.x + v0.y*v0.y + v0.z*v0.z + v0.w*v0.w
             + v1.x*v1.x + v1.y*v1.y + v1.z*v1.z + v1.w*v1.w;
    #pragma unroll
    for (int o = 16; o > 0; o >>= 1) {
        s  += __shfl_xor_sync(0xffffffffu, s,  o);
        ss += __shfl_xor_sync(0xffffffffu, ss, o);
    }
    float mu  = s * (1.0f / DIM);
    float var = ss * (1.0f / DIM) - mu * mu;
    float inv = rsqrtf(var + 1e-5f);

    const float4* wr = reinterpret_cast<const float4*>(w);
    const float4* br = reinterpret_cast<const float4*>(b);
    float4 w0 = wr[lane], w1 = wr[lane + 32];
    float4 b0 = br[lane], b1 = br[lane + 32];

    float4 o0, o1;
    o0.x = (v0.x - mu) * inv * w0.x + b0.x;
    o0.y = (v0.y - mu) * inv * w0.y + b0.y;
    o0.z = (v0.z - mu) * inv * w0.z + b0.z;
    o0.w = (v0.w - mu) * inv * w0.w + b0.w;
    o1.x = (v1.x - mu) * inv * w1.x + b1.x;
    o1.y = (v1.y - mu) * inv * w1.y + b1.y;
    o1.z = (v1.z - mu) * inv * w1.z + b1.z;
    o1.w = (v1.w - mu) * inv * w1.w + b1.w;

    float4* orow = reinterpret_cast<float4*>(out + (size_t)t * DIM);
    orow[lane]      = o0;
    orow[lane + 32] = o1;
}

// ---------------------------------------------------------------------------
// SIMT GEMM (x_proj only):  C[M,N] = A[M,K] @ W[N,K]^T
// ---------------------------------------------------------------------------
template<int BM, int BN, int BK, int TM, int TN>
__global__ void __launch_bounds__((BM/TM)*(BN/TN))
gemm_kernel(const float* __restrict__ A,
            const float* __restrict__ W,
            float* __restrict__ C0,
            int M, int N, int K)
{
    constexpr int THREADS = (BM / TM) * (BN / TN);
    constexpr int BKV = BK / 4;

    __shared__ float As[BK][BM + 4];
    __shared__ float Ws[BK][BN + 4];

    const int tid = threadIdx.x;
    const int tx  = tid % (BN / TN);
    const int ty  = tid / (BN / TN);
    const int m0  = blockIdx.y * BM;
    const int n0  = blockIdx.x * BN;

    float acc[TM][TN];
    #pragma unroll
    for (int i = 0; i < TM; i++)
        #pragma unroll
        for (int j = 0; j < TN; j++) acc[i][j] = 0.0f;

    for (int k0 = 0; k0 < K; k0 += BK) {
        constexpr int AV = BM * BK / 4;
        #pragma unroll
        for (int i = tid; i < AV; i += THREADS) {
            int r  = i / BKV;
            int c4 = i % BKV;
            float4 v = *reinterpret_cast<const float4*>(
                A + (size_t)(m0 + r) * K + k0 + c4 * 4);
            As[c4 * 4 + 0][r] = v.x;
            As[c4 * 4 + 1][r] = v.y;
            As[c4 * 4 + 2][r] = v.z;
            As[c4 * 4 + 3][r] = v.w;
        }
        constexpr int WV = BN * BK / 4;
        #pragma unroll
        for (int i = tid; i < WV; i += THREADS) {
            int r  = i / BKV;
            int c4 = i % BKV;
            float4 v = *reinterpret_cast<const float4*>(
                W + (size_t)(n0 + r) * K + k0 + c4 * 4);
            Ws[c4 * 4 + 0][r] = v.x;
            Ws[c4 * 4 + 1][r] = v.y;
            Ws[c4 * 4 + 2][r] = v.z;
            Ws[c4 * 4 + 3][r] = v.w;
        }
        __syncthreads();

        #pragma unroll
        for (int kk = 0; kk < BK; kk++) {
            float a[TM], bb[TN];
            #pragma unroll
            for (int i = 0; i < TM; i++) a[i]  = As[kk][ty * TM + i];
            #pragma unroll
            for (int j = 0; j < TN; j++) bb[j] = Ws[kk][tx * TN + j];
            #pragma unroll
            for (int i = 0; i < TM; i++)
                #pragma unroll
                for (int j = 0; j < TN; j++)
                    acc[i][j] = fmaf(a[i], bb[j], acc[i][j]);
        }
        __syncthreads();
    }

    #pragma unroll
    for (int i = 0; i < TM; i++) {
        int row = m0 + ty * TM + i;
        #pragma unroll
        for (int j = 0; j < TN; j++) {
            int col = n0 + tx * TN + j;
            C0[(size_t)row * N + col] = acc[i][j];
        }
    }
}

// ---------------------------------------------------------------------------
// Causal depthwise conv (DCONV=4) + bias + SiLU.  One thread per (token, ch).
// ---------------------------------------------------------------------------
__global__ void conv_kernel(const float* __restrict__ xin,
                            const float* __restrict__ cw,
                            const float* __restrict__ cb,
                            float* __restrict__ xc)
{
    int idx = blockIdx.x * blockDim.x + threadIdx.x;
    if (idx >= TOK * DIN) return;
    int c = idx % DIN;
    int t = idx / DIN;
    int l = t % LL;

    float w0 = cw[c * DCONV + 0];
    float w1 = cw[c * DCONV + 1];
    float w2 = cw[c * DCONV + 2];
    float w3 = cw[c * DCONV + 3];

    float acc = cb[c];
    if (l >= 3) acc = fmaf(xin[idx - 3 * DIN], w0, acc);
    if (l >= 2) acc = fmaf(xin[idx - 2 * DIN], w1, acc);
    if (l >= 1) acc = fmaf(xin[idx - 1 * DIN], w2, acc);
    acc = fmaf(xin[idx], w3, acc);
    xc[idx] = siluf(acc);
}

// ---------------------------------------------------------------------------
// dt = softplus( dbc[:, :DTRANK] @ dtw^T + dtb ).  One thread per (token, d).
// ---------------------------------------------------------------------------
__global__ void dt_kernel(const float* __restrict__ dbc,
                          const float* __restrict__ dtw,
                          const float* __restrict__ dtb,
                          float* __restrict__ dt)
{
    int idx = blockIdx.x * blockDim.x + threadIdx.x;
    if (idx >= TOK * DIN) return;
    int d = idx % DIN;
    int t = idx / DIN;

    const float* r  = dbc + (size_t)t * DBC_N;
    const float* wv = dtw + (size_t)d * DTRANK;
    float acc = dtb[d];
    #pragma unroll
    for (int i = 0; i < DTRANK; i++) acc = fmaf(r[i], wv[i], acc);
    dt[idx] = softplusf(acc);
}

// ---------------------------------------------------------------------------
// Selective scan + gating.
// 16 lanes per (b,d) channel, lane n holds state n. y via 4x shfl.xor reduce.
// ---------------------------------------------------------------------------
__global__ void __launch_bounds__(256)
scan_kernel(const float* __restrict__ dt,
            const float* __restrict__ dbc,
            const float* __restrict__ u,      // xc
            const float* __restrict__ A_log,  // (DIN, DSTATE) for this block
            const float* __restrict__ Dv,     // (DIN)
            const float* __restrict__ silz,
            float* __restrict__ g)
{
    int tid = threadIdx.x;
    int n   = tid & 15;
    int ch  = blockIdx.x * 16 + (tid >> 4);   // ch = b*DIN + d
    int b   = ch >> 9;                        // / DIN
    int d   = ch & (DIN - 1);

    float An = -__expf(A_log[d * DSTATE + n]);
    float Dd = Dv[d];
    float h  = 0.0f;
    int tbase = b * LL;

    #pragma unroll 4
    for (int l = 0; l < LL; l++) {
        int t = tbase + l;
        float dtv = dt[(size_t)t * DIN + d];
        float uv  = u [(size_t)t * DIN + d];
        float Bn  = dbc[(size_t)t * DBC_N + DTRANK + n];
        float Cn  = dbc[(size_t)t * DBC_N + DTRANK + DSTATE + n];

        float dA = __expf(dtv * An);
        h = fmaf(dA, h, dtv * Bn * uv);

        float p = h * Cn;
        p += __shfl_xor_sync(0xffffffffu, p, 8);
        p += __shfl_xor_sync(0xffffffffu, p, 4);
        p += __shfl_xor_sync(0xffffffffu, p, 2);
        p += __shfl_xor_sync(0xffffffffu, p, 1);

        if (n == 0) {
            float y = p + uv * Dd;
            g[(size_t)t * DIN + d] = y * silz[(size_t)t * DIN + d];
        }
    }
}

// ---------------------------------------------------------------------------
// Launcher
// ---------------------------------------------------------------------------
extern "C" void kernel_launch(void* const* d_in, const int* in_sizes, int n_in,
                              void* d_out, int out_size)
{
    const float* x    = (const float*)d_in[0];
    const float* ln_w = (const float*)d_in[1];
    const float* ln_b = (const float*)d_in[2];
    const float* in_w = (const float*)d_in[3];
    const float* in_b = (const float*)d_in[4];
    const float* cw   = (const float*)d_in[5];
    const float* cb   = (const float*)d_in[6];
    const float* xp_w = (const float*)d_in[7];
    const float* dt_w = (const float*)d_in[8];
    const float* dt_b = (const float*)d_in[9];
    const float* A_lg = (const float*)d_in[10];
    const float* Dv   = (const float*)d_in[11];
    const float* ow   = (const float*)d_in[12];

    float *p_h, *p_xin, *p_silz, *p_xc, *p_dbc, *p_dt, *p_g;
    cudaGetSymbolAddress((void**)&p_h,    g_h);
    cudaGetSymbolAddress((void**)&p_xin,  g_xin);
    cudaGetSymbolAddress((void**)&p_silz, g_silz);
    cudaGetSymbolAddress((void**)&p_xc,   g_xc);
    cudaGetSymbolAddress((void**)&p_dbc,  g_dbc);
    cudaGetSymbolAddress((void**)&p_dt,   g_dt);
    cudaGetSymbolAddress((void**)&p_g,    g_g);

    float* xres = (float*)d_out;  // running residual buffer (= final output)
    cudaMemcpyAsync(xres, x, (size_t)TOK * DIM * sizeof(float),
                    cudaMemcpyDeviceToDevice, 0);

    for (int nb = 0; nb < NBLK; nb++) {
        const float* lnw = ln_w + nb * DIM;
        const float* lnb = ln_b + nb * DIM;
        const float* inw = in_w + (size_t)nb * 2 * DIN * DIM;
        const float* inb = in_b + nb * 2 * DIN;
        const float* cwn = cw   + (size_t)nb * DIN * DCONV;
        const float* cbn = cb   + nb * DIN;
        const float* xpw = xp_w + (size_t)nb * DBC_N * DIN;
        const float* dtw = dt_w + (size_t)nb * DIN * DTRANK;
        const float* dtb = dt_b + nb * DIN;
        const float* alg = A_lg + (size_t)nb * DIN * DSTATE;
        const float* dvn = Dv   + nb * DIN;
        const float* own = ow   + (size_t)nb * DIM * DIN;

        // 1. LayerNorm (8 warps/block = 8 tokens/block)
        ln_kernel<<<TOK / 8, 256>>>(xres, lnw, lnb, p_h);

        // 2. in_proj GEMM (HMMA bf16 3-term): (8192,256)@(256,1024)
        gemm_mma<0, DIM><<<dim3(2 * DIN / 128, TOK / 128), 256>>>(
            p_h, inw, inb, p_xin, p_silz, 2 * DIN);

        // 3. Causal depthwise conv + SiLU
        conv_kernel<<<(TOK * DIN) / 256, 256>>>(p_xin, cwn, cbn, p_xc);

        // 4. x_proj GEMM (SIMT, BM=32 -> 256 CTAs for full-chip occupancy)
        gemm_kernel<32, 48, 16, 2, 3>
            <<<dim3(1, TOK / 32), 256>>>(
                p_xc, xpw, p_dbc, TOK, DBC_N, DIN);

        // 5. dt projection + softplus
        dt_kernel<<<(TOK * DIN) / 256, 256>>>(p_dbc, dtw, dtb, p_dt);

        // 6. Selective scan + D skip + gating
        scan_kernel<<<(BB * DIN) / 16, 256>>>(
            p_dt, p_dbc, p_xc, alg, dvn, p_silz, p_g);

        // 7. out_proj GEMM (HMMA) + residual: xres += g @ ow^T
        gemm_mma<2, DIN><<<dim3(DIM / 128, TOK / 128), 256>>>(
            p_g, own, nullptr, xres, xres, DIM);
    }
}